// round 1
// baseline (speedup 1.0000x reference)
#include <cuda_runtime.h>
#include <math.h>

#define BATCH 4
#define LSEQ  8192
#define DIM   1024
#define KSEL  6144          // int(8192 * 0.75)
#define NTOK  (BATCH * LSEQ)

// Scratch (no device mallocs allowed)
__device__ float g_scores[NTOK];
__device__ int   g_flags[NTOK];

// ---------------------------------------------------------------------------
// Kernel 1: router scores  s[t] = dot(x[t,:], w_router)   (fp32, warp/token)
// ---------------------------------------------------------------------------
__global__ __launch_bounds__(256) void scores_kernel(
    const float* __restrict__ x, const float* __restrict__ wr)
{
    int warp = (blockIdx.x * blockDim.x + threadIdx.x) >> 5;
    int lane = threadIdx.x & 31;
    if (warp >= NTOK) return;
    const float4* xr = (const float4*)(x + (size_t)warp * DIM);
    const float4* w4 = (const float4*)wr;
    float s = 0.f;
#pragma unroll
    for (int i = 0; i < 8; i++) {
        float4 a = xr[lane + i * 32];
        float4 b = w4[lane + i * 32];
        s += a.x * b.x + a.y * b.y + a.z * b.z + a.w * b.w;
    }
#pragma unroll
    for (int o = 16; o; o >>= 1) s += __shfl_xor_sync(0xFFFFFFFFu, s, o);
    if (lane == 0) g_scores[warp] = s;
}

// ---------------------------------------------------------------------------
// Kernel 2: top-k membership by stable rank counting (exact top_k semantics)
// grid = (chunks=32, rows=4), 256 threads; each thread handles one element.
// ---------------------------------------------------------------------------
__global__ __launch_bounds__(256) void flags_kernel()
{
    __shared__ float sh[LSEQ];
    int row = blockIdx.y;
    int tid = threadIdx.x;
    const float* srow = g_scores + row * LSEQ;
    for (int i = tid; i < LSEQ; i += 256) sh[i] = srow[i];
    __syncthreads();

    int l  = blockIdx.x * 256 + tid;
    float sl = sh[l];
    int cnt = 0;
#pragma unroll 8
    for (int j = 0; j < LSEQ; j++) {
        float v = sh[j];
        cnt += (v > sl) || (v == sl && j < l);
    }
    g_flags[row * LSEQ + l] = (cnt < KSEL) ? 1 : 0;
}

// ---------------------------------------------------------------------------
// Kernel 3: fused GEMM + gelu + select epilogue.
// out[t,:] = selected(t) ? gelu(x[t,:] @ W) : x[t,:]
// 128x128 tile, BK=8, 256 threads, 8x8 micro-tile (4+4 split), double-buffered.
// M = 32768 (all tokens; B*L contiguous), N = K = 1024.
// ---------------------------------------------------------------------------
#define BM 128
#define BN 128
#define BK 8

__device__ __forceinline__ float gelu_tanh(float v)
{
    // jax.nn.gelu default (approximate=True)
    float u = 0.7978845608028654f * (v + 0.044715f * v * v * v);
    return 0.5f * v * (1.0f + tanhf(u));
}

__global__ __launch_bounds__(256) void gemm_select_kernel(
    const float* __restrict__ x, const float* __restrict__ w,
    float* __restrict__ out)
{
    __shared__ float As[2][BK][BM];
    __shared__ float Bs[2][BK][BN];

    const int tid   = threadIdx.x;
    const int mBase = blockIdx.y * BM;
    const int nBase = blockIdx.x * BN;

    // A-tile load mapping: 128 rows x 8 k, float4 per thread
    const int aRow = tid >> 1;
    const int aK   = (tid & 1) * 4;
    // B-tile load mapping: 8 k-rows x 128 n, float4 per thread
    const int bK   = tid >> 5;
    const int bN   = (tid & 31) * 4;

    const float* aPtr = x + (size_t)(mBase + aRow) * DIM + aK;
    const float* bPtr = w + (size_t)bK * DIM + nBase + bN;

    const int ty = tid >> 4;   // 0..15
    const int tx = tid & 15;   // 0..15

    float acc[8][8];
#pragma unroll
    for (int i = 0; i < 8; i++)
#pragma unroll
        for (int j = 0; j < 8; j++) acc[i][j] = 0.f;

    // preload tile 0
    float4 aReg = *(const float4*)(aPtr);
    float4 bReg = *(const float4*)(bPtr);
    As[0][aK + 0][aRow] = aReg.x;
    As[0][aK + 1][aRow] = aReg.y;
    As[0][aK + 2][aRow] = aReg.z;
    As[0][aK + 3][aRow] = aReg.w;
    *(float4*)&Bs[0][bK][bN] = bReg;
    __syncthreads();

    const int NK = DIM / BK;  // 128 k-tiles
#pragma unroll 1
    for (int kt = 0; kt < NK; kt++) {
        int cur = kt & 1, nxt = cur ^ 1;
        if (kt + 1 < NK) {
            aReg = *(const float4*)(aPtr + (kt + 1) * BK);
            bReg = *(const float4*)(bPtr + (size_t)(kt + 1) * BK * DIM);
        }
#pragma unroll
        for (int k = 0; k < BK; k++) {
            float a[8], b[8];
            *(float4*)&a[0] = *(const float4*)&As[cur][k][ty * 4];
            *(float4*)&a[4] = *(const float4*)&As[cur][k][64 + ty * 4];
            *(float4*)&b[0] = *(const float4*)&Bs[cur][k][tx * 4];
            *(float4*)&b[4] = *(const float4*)&Bs[cur][k][64 + tx * 4];
#pragma unroll
            for (int i = 0; i < 8; i++)
#pragma unroll
                for (int j = 0; j < 8; j++)
                    acc[i][j] += a[i] * b[j];
        }
        if (kt + 1 < NK) {
            As[nxt][aK + 0][aRow] = aReg.x;
            As[nxt][aK + 1][aRow] = aReg.y;
            As[nxt][aK + 2][aRow] = aReg.z;
            As[nxt][aK + 3][aRow] = aReg.w;
            *(float4*)&Bs[nxt][bK][bN] = bReg;
        }
        __syncthreads();
    }

    // Epilogue: gelu for selected tokens, pass-through x otherwise.
#pragma unroll
    for (int i = 0; i < 8; i++) {
        int r = mBase + ((i < 4) ? (ty * 4 + i) : (64 + ty * 4 + i - 4));
        int flag = g_flags[r];
        float*       orow = out + (size_t)r * DIM + nBase;
        const float* xrow = x   + (size_t)r * DIM + nBase;
#pragma unroll
        for (int jh = 0; jh < 2; jh++) {
            int c = jh ? (64 + tx * 4) : (tx * 4);
            float4 v;
            if (flag) {
                v.x = gelu_tanh(acc[i][jh * 4 + 0]);
                v.y = gelu_tanh(acc[i][jh * 4 + 1]);
                v.z = gelu_tanh(acc[i][jh * 4 + 2]);
                v.w = gelu_tanh(acc[i][jh * 4 + 3]);
            } else {
                v = *(const float4*)(xrow + c);
            }
            *(float4*)(orow + c) = v;
        }
    }
}

// ---------------------------------------------------------------------------
extern "C" void kernel_launch(void* const* d_in, const int* in_sizes, int n_in,
                              void* d_out, int out_size)
{
    const float* x  = (const float*)d_in[0];   // [4,8192,1024]
    const float* wr = (const float*)d_in[1];   // [1024]
    const float* wb = (const float*)d_in[2];   // [1024,1024]
    float* out = (float*)d_out;

    scores_kernel<<<NTOK / 8, 256>>>(x, wr);                 // 8 warps/block
    flags_kernel<<<dim3(LSEQ / 256, BATCH), 256>>>();
    gemm_select_kernel<<<dim3(DIM / BN, NTOK / BM), 256>>>(x, wb, out);
}

// round 3
// speedup vs baseline: 2.1430x; 2.1430x over previous
#include <cuda_runtime.h>
#include <cuda_bf16.h>
#include <math.h>
#include <cstdint>

#define BATCH 4
#define LSEQ  8192
#define DIM   1024
#define KSEL  6144
#define NTOK  (BATCH * LSEQ)

// ---------------- scratch (no mallocs allowed) ----------------
__device__ float          g_scores[NTOK];
__device__ int            g_flags[NTOK];
__device__ __nv_bfloat16  g_xhi[(size_t)NTOK * DIM];
__device__ __nv_bfloat16  g_xlo[(size_t)NTOK * DIM];
__device__ __nv_bfloat16  g_whiT[DIM * DIM];
__device__ __nv_bfloat16  g_wloT[DIM * DIM];

// ---------------- helpers ----------------
__device__ __forceinline__ uint32_t smem_u32(const void* p) {
    uint32_t a;
    asm("{ .reg .u64 t; cvta.to.shared.u64 t, %1; cvt.u32.u64 %0, t; }"
        : "=r"(a) : "l"(p));
    return a;
}
#define SW128(off) ((off) ^ (((off) >> 3) & 0x70))

#define CP_ASYNC16(smem, gmem)                                               \
    asm volatile("cp.async.cg.shared.global [%0], [%1], 16;"                 \
                 :: "r"(smem), "l"(gmem) : "memory")
#define CP_COMMIT()  asm volatile("cp.async.commit_group;" ::: "memory")
#define CP_WAIT(n)   asm volatile("cp.async.wait_group %0;" :: "n"(n) : "memory")

#define LDSM4(r0, r1, r2, r3, addr)                                          \
    asm volatile("ldmatrix.sync.aligned.m8n8.x4.shared.b16 {%0,%1,%2,%3}, [%4];" \
                 : "=r"(r0), "=r"(r1), "=r"(r2), "=r"(r3) : "r"(addr))

#define MMA_BF16(c, a, b)                                                    \
    asm volatile("mma.sync.aligned.m16n8k16.row.col.f32.bf16.bf16.f32 "      \
                 "{%0,%1,%2,%3}, {%4,%5,%6,%7}, {%8,%9}, {%0,%1,%2,%3};"     \
                 : "+f"((c)[0]), "+f"((c)[1]), "+f"((c)[2]), "+f"((c)[3])    \
                 : "r"((a)[0]), "r"((a)[1]), "r"((a)[2]), "r"((a)[3]),       \
                   "r"((b)[0]), "r"((b)[1]))

__device__ __forceinline__ float gelu_tanh(float v)
{
    float u = 0.7978845608028654f * (v + 0.044715f * v * v * v);
    return 0.5f * v * (1.0f + tanhf(u));
}

// ---------------------------------------------------------------------------
// Kernel 1: router scores + x -> (hi, lo) bf16 split, fused (x read once)
// ---------------------------------------------------------------------------
__global__ __launch_bounds__(256) void scores_cvt_kernel(
    const float* __restrict__ x, const float* __restrict__ wr)
{
    int warp = (blockIdx.x * blockDim.x + threadIdx.x) >> 5;
    int lane = threadIdx.x & 31;
    if (warp >= NTOK) return;
    const float4* xr = (const float4*)(x + (size_t)warp * DIM);
    const float4* w4 = (const float4*)wr;
    uint2* hrow = (uint2*)(g_xhi + (size_t)warp * DIM);
    uint2* lrow = (uint2*)(g_xlo + (size_t)warp * DIM);
    float s = 0.f;
#pragma unroll
    for (int i = 0; i < 8; i++) {
        int d4 = lane + i * 32;
        float4 a = xr[d4];
        float4 b = w4[d4];
        s += a.x * b.x + a.y * b.y + a.z * b.z + a.w * b.w;
        __nv_bfloat16 h0 = __float2bfloat16(a.x), h1 = __float2bfloat16(a.y);
        __nv_bfloat16 h2 = __float2bfloat16(a.z), h3 = __float2bfloat16(a.w);
        __nv_bfloat16 l0 = __float2bfloat16(a.x - __bfloat162float(h0));
        __nv_bfloat16 l1 = __float2bfloat16(a.y - __bfloat162float(h1));
        __nv_bfloat16 l2 = __float2bfloat16(a.z - __bfloat162float(h2));
        __nv_bfloat16 l3 = __float2bfloat16(a.w - __bfloat162float(h3));
        uint2 hp, lp;
        hp.x = ((uint32_t)__bfloat16_as_ushort(h1) << 16) | __bfloat16_as_ushort(h0);
        hp.y = ((uint32_t)__bfloat16_as_ushort(h3) << 16) | __bfloat16_as_ushort(h2);
        lp.x = ((uint32_t)__bfloat16_as_ushort(l1) << 16) | __bfloat16_as_ushort(l0);
        lp.y = ((uint32_t)__bfloat16_as_ushort(l3) << 16) | __bfloat16_as_ushort(l2);
        hrow[d4] = hp;
        lrow[d4] = lp;
    }
#pragma unroll
    for (int o = 16; o; o >>= 1) s += __shfl_xor_sync(0xFFFFFFFFu, s, o);
    if (lane == 0) g_scores[warp] = s;
}

// ---------------------------------------------------------------------------
// Kernel 2: W[K,N] -> W^T hi/lo bf16 [N,K]  (tiled transpose, tiny)
// ---------------------------------------------------------------------------
__global__ __launch_bounds__(256) void wcvt_kernel(const float* __restrict__ w)
{
    __shared__ float tile[32][33];
    int tx = threadIdx.x & 31, ty = threadIdx.x >> 5;
    int n0 = blockIdx.x * 32, k0 = blockIdx.y * 32;
#pragma unroll
    for (int j = 0; j < 4; j++)
        tile[ty + j * 8][tx] = w[(size_t)(k0 + ty + j * 8) * DIM + n0 + tx];
    __syncthreads();
#pragma unroll
    for (int j = 0; j < 4; j++) {
        int n = n0 + ty + j * 8, k = k0 + tx;
        float v = tile[tx][ty + j * 8];
        __nv_bfloat16 h = __float2bfloat16(v);
        __nv_bfloat16 l = __float2bfloat16(v - __bfloat162float(h));
        g_whiT[(size_t)n * DIM + k] = h;
        g_wloT[(size_t)n * DIM + k] = l;
    }
}

// ---------------------------------------------------------------------------
// Kernel 3: stable top-k membership by rank counting
// ---------------------------------------------------------------------------
__global__ __launch_bounds__(256) void flags_kernel()
{
    __shared__ float sh[LSEQ];
    int row = blockIdx.y;
    int tid = threadIdx.x;
    const float* srow = g_scores + row * LSEQ;
    for (int i = tid; i < LSEQ; i += 256) sh[i] = srow[i];
    __syncthreads();
    int l = blockIdx.x * 256 + tid;
    float sl = sh[l];
    int cnt = 0;
#pragma unroll 8
    for (int j = 0; j < LSEQ; j++) {
        float v = sh[j];
        cnt += (v > sl) || (v == sl && j < l);
    }
    g_flags[row * LSEQ + l] = (cnt < KSEL) ? 1 : 0;
}

// ---------------------------------------------------------------------------
// Kernel 4: mma.sync bf16 split GEMM + gelu/select epilogue
// CTA: 128x128 tile, BK=64 bf16 (SW128 rows), 8 warps (2m x 4n), 64x32/warp.
// 48 K-chunks: phase0 x_hi@W_hi, phase1 x_lo@W_hi, phase2 x_hi@W_lo.
// cp.async double buffer. Epilogue from registers.
// ---------------------------------------------------------------------------
#define BM 128
#define BN 128
#define KC 64
#define NCHUNK 48
#define TILE_BYTES (128 * 128)          // 16 KB (128 rows x 128B)
#define SMEM_DYN (1024 + 4 * TILE_BYTES)

__device__ __forceinline__ void fill_tile_async(
    uint32_t sA, uint32_t sB,
    const __nv_bfloat16* __restrict__ Asrc,
    const __nv_bfloat16* __restrict__ Bsrc, int tid)
{
#pragma unroll
    for (int it = 0; it < 4; it++) {
        int idx = tid + it * 256;
        int m = idx >> 3, kq = (idx & 7) * 8;
        CP_ASYNC16(sA + SW128((uint32_t)(m * 128 + kq * 2)),
                   Asrc + (size_t)m * DIM + kq);
    }
#pragma unroll
    for (int it = 0; it < 4; it++) {
        int idx = tid + it * 256;
        int n = idx >> 3, kq = (idx & 7) * 8;
        CP_ASYNC16(sB + SW128((uint32_t)(n * 128 + kq * 2)),
                   Bsrc + (size_t)n * DIM + kq);
    }
    CP_COMMIT();
}

__global__ __launch_bounds__(256) void gemm_mma_kernel(
    const float* __restrict__ x, float* __restrict__ out)
{
    extern __shared__ char dsm[];
    const int tid  = threadIdx.x;
    const int wid  = tid >> 5;
    const int lane = tid & 31;
    const int wm   = wid & 1;       // 0..1 -> 64 rows
    const int wn   = wid >> 1;      // 0..3 -> 32 cols
    const int m0   = blockIdx.y * BM;
    const int n0   = blockIdx.x * BN;

    uint32_t base = (smem_u32(dsm) + 1023u) & ~1023u;
    uint32_t aBuf[2] = { base,                  base + 2 * TILE_BYTES };
    uint32_t bBuf[2] = { base + TILE_BYTES,     base + 3 * TILE_BYTES };

    float acc[4][4][4];
#pragma unroll
    for (int i = 0; i < 4; i++)
#pragma unroll
        for (int j = 0; j < 4; j++)
#pragma unroll
            for (int q = 0; q < 4; q++) acc[i][j][q] = 0.f;

    // precomputed ldmatrix lane offsets (byte offsets before swizzle)
    const uint32_t aLaneOff =
        (uint32_t)(((lane & 7) + ((lane >> 3) & 1) * 8) * 128 + (lane >> 4) * 16);
    const uint32_t bLaneOff =
        (uint32_t)(((lane & 7) + ((lane >> 4) & 1) * 8) * 128 + ((lane >> 3) & 1) * 16);

    // chunk source pointers
    auto asrc = [&](int c) {
        int p = c >> 4, kc = (c & 15) * KC;
        return (p == 1 ? g_xlo : g_xhi) + (size_t)m0 * DIM + kc;
    };
    auto bsrc = [&](int c) {
        int p = c >> 4, kc = (c & 15) * KC;
        return (p == 2 ? g_wloT : g_whiT) + (size_t)n0 * DIM + kc;
    };

    fill_tile_async(aBuf[0], bBuf[0], asrc(0), bsrc(0), tid);

#pragma unroll 1
    for (int c = 0; c < NCHUNK; c++) {
        const int buf = c & 1;
        if (c + 1 < NCHUNK) {
            fill_tile_async(aBuf[buf ^ 1], bBuf[buf ^ 1], asrc(c + 1), bsrc(c + 1), tid);
            CP_WAIT(1);
        } else {
            CP_WAIT(0);
        }
        __syncthreads();

        const uint32_t aB = aBuf[buf], bB = bBuf[buf];
#pragma unroll
        for (int ks = 0; ks < 4; ks++) {
            uint32_t afr[4][4];
#pragma unroll
            for (int mt = 0; mt < 4; mt++) {
                uint32_t off = (uint32_t)((wm * 64 + mt * 16) * 128 + ks * 32) + aLaneOff;
                LDSM4(afr[mt][0], afr[mt][1], afr[mt][2], afr[mt][3], aB + SW128(off));
            }
            uint32_t bfr[4][2];
#pragma unroll
            for (int np = 0; np < 2; np++) {
                uint32_t off = (uint32_t)((wn * 32 + np * 16) * 128 + ks * 32) + bLaneOff;
                LDSM4(bfr[2 * np][0], bfr[2 * np][1],
                      bfr[2 * np + 1][0], bfr[2 * np + 1][1], bB + SW128(off));
            }
#pragma unroll
            for (int mt = 0; mt < 4; mt++)
#pragma unroll
                for (int nt = 0; nt < 4; nt++)
                    MMA_BF16(acc[mt][nt], afr[mt], bfr[nt]);
        }
        __syncthreads();
    }

    // Epilogue: rows r = m0 + wm*64 + mt*16 + lane/4 (+8), cols n0 + wn*32 + nt*8 + (lane%3..)*2
    const int colBase = n0 + wn * 32 + (lane & 3) * 2;
#pragma unroll
    for (int mt = 0; mt < 4; mt++) {
        int r0 = m0 + wm * 64 + mt * 16 + (lane >> 2);
        int r1 = r0 + 8;
        int f0 = g_flags[r0], f1 = g_flags[r1];
        float*       o0 = out + (size_t)r0 * DIM;
        float*       o1 = out + (size_t)r1 * DIM;
        const float* x0 = x   + (size_t)r0 * DIM;
        const float* x1 = x   + (size_t)r1 * DIM;
#pragma unroll
        for (int nt = 0; nt < 4; nt++) {
            int cc = colBase + nt * 8;
            float2 v0, v1;
            if (f0) {
                v0.x = gelu_tanh(acc[mt][nt][0]);
                v0.y = gelu_tanh(acc[mt][nt][1]);
            } else {
                v0 = *(const float2*)(x0 + cc);
            }
            if (f1) {
                v1.x = gelu_tanh(acc[mt][nt][2]);
                v1.y = gelu_tanh(acc[mt][nt][3]);
            } else {
                v1 = *(const float2*)(x1 + cc);
            }
            *(float2*)(o0 + cc) = v0;
            *(float2*)(o1 + cc) = v1;
        }
    }
}

// ---------------------------------------------------------------------------
extern "C" void kernel_launch(void* const* d_in, const int* in_sizes, int n_in,
                              void* d_out, int out_size)
{
    const float* x  = (const float*)d_in[0];   // [4,8192,1024]
    const float* wr = (const float*)d_in[1];   // [1024]
    const float* wb = (const float*)d_in[2];   // [1024,1024]
    float* out = (float*)d_out;

    cudaFuncSetAttribute(gemm_mma_kernel,
                         cudaFuncAttributeMaxDynamicSharedMemorySize, SMEM_DYN);

    scores_cvt_kernel<<<NTOK / 8, 256>>>(x, wr);
    wcvt_kernel<<<dim3(32, 32), 256>>>(wb);
    flags_kernel<<<dim3(LSEQ / 256, BATCH), 256>>>();
    gemm_mma_kernel<<<dim3(DIM / BN, NTOK / BM), 256, SMEM_DYN>>>(x, out);
}

// round 4
// speedup vs baseline: 4.4657x; 2.0838x over previous
#include <cuda_runtime.h>
#include <cuda_fp16.h>
#include <math.h>
#include <cstdint>

#define BATCH 4
#define LSEQ  8192
#define DIM   1024
#define KSEL  6144
#define NTOK  (BATCH * LSEQ)
#define MBLK_PER_ROW (KSEL / 128)     // 48

// ---------------- scratch ----------------
__device__ float   g_scores[NTOK];
__device__ int     g_flags[NTOK];
__device__ int     g_idx[BATCH * KSEL];
__device__ int     g_cnt[BATCH];
__device__ __half  g_xh[(size_t)NTOK * DIM];
__device__ __half  g_whT[DIM * DIM];

// ---------------- helpers ----------------
__device__ __forceinline__ uint32_t smem_u32(const void* p) {
    uint32_t a;
    asm("{ .reg .u64 t; cvta.to.shared.u64 t, %1; cvt.u32.u64 %0, t; }"
        : "=r"(a) : "l"(p));
    return a;
}
#define SW128(off) ((off) ^ (((off) >> 3) & 0x70))

#define CP_ASYNC16(smem, gmem)                                               \
    asm volatile("cp.async.cg.shared.global [%0], [%1], 16;"                 \
                 :: "r"(smem), "l"(gmem) : "memory")
#define CP_COMMIT()  asm volatile("cp.async.commit_group;" ::: "memory")
#define CP_WAIT(n)   asm volatile("cp.async.wait_group %0;" :: "n"(n) : "memory")

#define LDSM4(r0, r1, r2, r3, addr)                                          \
    asm volatile("ldmatrix.sync.aligned.m8n8.x4.shared.b16 {%0,%1,%2,%3}, [%4];" \
                 : "=r"(r0), "=r"(r1), "=r"(r2), "=r"(r3) : "r"(addr))

#define MMA_FP16(c, a, b)                                                    \
    asm volatile("mma.sync.aligned.m16n8k16.row.col.f32.f16.f16.f32 "        \
                 "{%0,%1,%2,%3}, {%4,%5,%6,%7}, {%8,%9}, {%0,%1,%2,%3};"     \
                 : "+f"((c)[0]), "+f"((c)[1]), "+f"((c)[2]), "+f"((c)[3])    \
                 : "r"((a)[0]), "r"((a)[1]), "r"((a)[2]), "r"((a)[3]),       \
                   "r"((b)[0]), "r"((b)[1]))

__device__ __forceinline__ float gelu_tanh(float v)
{
    float u = 0.7978845608028654f * (v + 0.044715f * v * v * v);
    return 0.5f * v * (1.0f + tanhf(u));
}

// ---------------------------------------------------------------------------
// Kernel 1: router scores + x -> fp16, fused (x read once)
// ---------------------------------------------------------------------------
__global__ __launch_bounds__(256) void scores_cvt_kernel(
    const float* __restrict__ x, const float* __restrict__ wr)
{
    int warp = (blockIdx.x * blockDim.x + threadIdx.x) >> 5;
    int lane = threadIdx.x & 31;
    if (warp >= NTOK) return;
    const float4* xr = (const float4*)(x + (size_t)warp * DIM);
    const float4* w4 = (const float4*)wr;
    uint2* hrow = (uint2*)(g_xh + (size_t)warp * DIM);
    float s = 0.f;
#pragma unroll
    for (int i = 0; i < 8; i++) {
        int d4 = lane + i * 32;
        float4 a = xr[d4];
        float4 b = w4[d4];
        s += a.x * b.x + a.y * b.y + a.z * b.z + a.w * b.w;
        __half2 p0 = __floats2half2_rn(a.x, a.y);
        __half2 p1 = __floats2half2_rn(a.z, a.w);
        uint2 hp;
        hp.x = *(uint32_t*)&p0;
        hp.y = *(uint32_t*)&p1;
        hrow[d4] = hp;
    }
#pragma unroll
    for (int o = 16; o; o >>= 1) s += __shfl_xor_sync(0xFFFFFFFFu, s, o);
    if (lane == 0) g_scores[warp] = s;
}

// ---------------------------------------------------------------------------
// Kernel 2: W[K,N] -> W^T fp16 [N,K]; block 0 also zeroes counters
// ---------------------------------------------------------------------------
__global__ __launch_bounds__(256) void wcvt_kernel(const float* __restrict__ w)
{
    if (blockIdx.x == 0 && blockIdx.y == 0 && threadIdx.x < BATCH)
        g_cnt[threadIdx.x] = 0;
    __shared__ float tile[32][33];
    int tx = threadIdx.x & 31, ty = threadIdx.x >> 5;
    int n0 = blockIdx.x * 32, k0 = blockIdx.y * 32;
#pragma unroll
    for (int j = 0; j < 4; j++)
        tile[ty + j * 8][tx] = w[(size_t)(k0 + ty + j * 8) * DIM + n0 + tx];
    __syncthreads();
#pragma unroll
    for (int j = 0; j < 4; j++) {
        int n = n0 + ty + j * 8, k = k0 + tx;
        g_whT[(size_t)n * DIM + k] = __float2half_rn(tile[tx][ty + j * 8]);
    }
}

// ---------------------------------------------------------------------------
// Kernel 3: stable top-k rank counting + compacted index append
// ---------------------------------------------------------------------------
__global__ __launch_bounds__(256) void flags_kernel()
{
    __shared__ float sh[LSEQ];
    int row = blockIdx.y;
    int tid = threadIdx.x;
    const float* srow = g_scores + row * LSEQ;
    for (int i = tid; i < LSEQ; i += 256) sh[i] = srow[i];
    __syncthreads();
    int l = blockIdx.x * 256 + tid;
    float sl = sh[l];
    int cnt = 0;
#pragma unroll 8
    for (int j = 0; j < LSEQ; j++) {
        float v = sh[j];
        cnt += (v > sl) || (v == sl && j < l);
    }
    int sel = (cnt < KSEL) ? 1 : 0;
    g_flags[row * LSEQ + l] = sel;
    if (sel) {
        int pos = atomicAdd(&g_cnt[row], 1);
        g_idx[row * KSEL + pos] = row * LSEQ + l;   // global token id
    }
}

// ---------------------------------------------------------------------------
// Kernel 4: pass-through copy for unselected tokens (warp per token)
// ---------------------------------------------------------------------------
__global__ __launch_bounds__(256) void copy_kernel(
    const float* __restrict__ x, float* __restrict__ out)
{
    int warp = (blockIdx.x * blockDim.x + threadIdx.x) >> 5;
    int lane = threadIdx.x & 31;
    if (warp >= NTOK) return;
    if (g_flags[warp]) return;
    const float4* src = (const float4*)(x + (size_t)warp * DIM);
    float4*       dst = (float4*)(out + (size_t)warp * DIM);
#pragma unroll
    for (int i = 0; i < 8; i++) dst[lane + i * 32] = src[lane + i * 32];
}

// ---------------------------------------------------------------------------
// Kernel 5: compacted fp16 mma.sync GEMM + gelu scatter epilogue
// CTA: 128x256 tile, 512 threads (16 warps, 4m x 4n; warp tile 32x64).
// KC=64 fp16 (128B SW128 rows); 16 K-chunks, cp.async double buffer.
// A rows gathered via g_idx (block's 128 indices cached in smem).
// ---------------------------------------------------------------------------
#define BN 256
#define KC 64
#define NCHUNK (DIM / KC)               // 16
#define A_BYTES (128 * 128)             // 16 KB
#define B_BYTES (BN * 128)              // 32 KB
#define SMEM_DYN (1024 + 2 * (A_BYTES + B_BYTES))   // ~97 KB

__global__ __launch_bounds__(512) void gemm_mma_kernel(float* __restrict__ out)
{
    extern __shared__ char dsm[];
    __shared__ int s_idx[128];

    const int tid  = threadIdx.x;
    const int wid  = tid >> 5;
    const int lane = tid & 31;
    const int wm   = wid & 3;       // 0..3 -> 32 rows each
    const int wn   = wid >> 2;      // 0..3 -> 64 cols each
    const int n0   = blockIdx.x * BN;
    const int b    = blockIdx.y / MBLK_PER_ROW;
    const int mblk = blockIdx.y % MBLK_PER_ROW;

    if (tid < 128) s_idx[tid] = g_idx[b * KSEL + mblk * 128 + tid];
    __syncthreads();

    uint32_t base = (smem_u32(dsm) + 1023u) & ~1023u;
    uint32_t aBuf[2] = { base,                       base + A_BYTES + B_BYTES };
    uint32_t bBuf[2] = { base + A_BYTES,             base + 2 * A_BYTES + B_BYTES };

    float acc[2][8][4];
#pragma unroll
    for (int i = 0; i < 2; i++)
#pragma unroll
        for (int j = 0; j < 8; j++)
#pragma unroll
            for (int q = 0; q < 4; q++) acc[i][j][q] = 0.f;

    const uint32_t aLaneOff =
        (uint32_t)(((lane & 7) + ((lane >> 3) & 1) * 8) * 128 + (lane >> 4) * 16);
    const uint32_t bLaneOff =
        (uint32_t)(((lane & 7) + ((lane >> 4) & 1) * 8) * 128 + ((lane >> 3) & 1) * 16);

    auto fill = [&](int c, int buf) {
        int kc = c * KC;
#pragma unroll
        for (int it = 0; it < 2; it++) {          // A: 128 rows x 128B
            int idx = tid + it * 512;
            int m = idx >> 3, kq = (idx & 7) * 8;
            int t = s_idx[m];
            CP_ASYNC16(aBuf[buf] + SW128((uint32_t)(m * 128 + kq * 2)),
                       g_xh + (size_t)t * DIM + kc + kq);
        }
#pragma unroll
        for (int it = 0; it < 4; it++) {          // B: 256 rows x 128B
            int idx = tid + it * 512;
            int n = idx >> 3, kq = (idx & 7) * 8;
            CP_ASYNC16(bBuf[buf] + SW128((uint32_t)(n * 128 + kq * 2)),
                       g_whT + (size_t)(n0 + n) * DIM + kc + kq);
        }
        CP_COMMIT();
    };

    fill(0, 0);

#pragma unroll 1
    for (int c = 0; c < NCHUNK; c++) {
        const int buf = c & 1;
        if (c + 1 < NCHUNK) { fill(c + 1, buf ^ 1); CP_WAIT(1); }
        else                { CP_WAIT(0); }
        __syncthreads();

        const uint32_t aB = aBuf[buf], bB = bBuf[buf];
#pragma unroll
        for (int ks = 0; ks < 4; ks++) {
            uint32_t afr[2][4];
#pragma unroll
            for (int mt = 0; mt < 2; mt++) {
                uint32_t off = (uint32_t)((wm * 32 + mt * 16) * 128 + ks * 32) + aLaneOff;
                LDSM4(afr[mt][0], afr[mt][1], afr[mt][2], afr[mt][3], aB + SW128(off));
            }
            uint32_t bfr[8][2];
#pragma unroll
            for (int np = 0; np < 4; np++) {
                uint32_t off = (uint32_t)((wn * 64 + np * 16) * 128 + ks * 32) + bLaneOff;
                LDSM4(bfr[2 * np][0], bfr[2 * np][1],
                      bfr[2 * np + 1][0], bfr[2 * np + 1][1], bB + SW128(off));
            }
#pragma unroll
            for (int mt = 0; mt < 2; mt++)
#pragma unroll
                for (int nt = 0; nt < 8; nt++)
                    MMA_FP16(acc[mt][nt], afr[mt], bfr[nt]);
        }
        __syncthreads();
    }

    // Epilogue: scatter gelu(acc) to out rows via s_idx (all rows selected).
    const int colBase = n0 + wn * 64 + (lane & 3) * 2;
#pragma unroll
    for (int mt = 0; mt < 2; mt++) {
        int rl0 = wm * 32 + mt * 16 + (lane >> 2);
        int t0 = s_idx[rl0];
        int t1 = s_idx[rl0 + 8];
        float* o0 = out + (size_t)t0 * DIM;
        float* o1 = out + (size_t)t1 * DIM;
#pragma unroll
        for (int nt = 0; nt < 8; nt++) {
            int cc = colBase + nt * 8;
            float2 v0, v1;
            v0.x = gelu_tanh(acc[mt][nt][0]);
            v0.y = gelu_tanh(acc[mt][nt][1]);
            v1.x = gelu_tanh(acc[mt][nt][2]);
            v1.y = gelu_tanh(acc[mt][nt][3]);
            *(float2*)(o0 + cc) = v0;
            *(float2*)(o1 + cc) = v1;
        }
    }
}

// ---------------------------------------------------------------------------
extern "C" void kernel_launch(void* const* d_in, const int* in_sizes, int n_in,
                              void* d_out, int out_size)
{
    const float* x  = (const float*)d_in[0];   // [4,8192,1024]
    const float* wr = (const float*)d_in[1];   // [1024]
    const float* wb = (const float*)d_in[2];   // [1024,1024]
    float* out = (float*)d_out;

    cudaFuncSetAttribute(gemm_mma_kernel,
                         cudaFuncAttributeMaxDynamicSharedMemorySize, SMEM_DYN);

    scores_cvt_kernel<<<NTOK / 8, 256>>>(x, wr);
    wcvt_kernel<<<dim3(32, 32), 256>>>(wb);
    flags_kernel<<<dim3(LSEQ / 256, BATCH), 256>>>();
    copy_kernel<<<NTOK / 8, 256>>>(x, out);
    gemm_mma_kernel<<<dim3(DIM / BN, BATCH * MBLK_PER_ROW), 512, SMEM_DYN>>>(out);
}